// round 3
// baseline (speedup 1.0000x reference)
#include <cuda_runtime.h>

#define UN      100000
#define IIN     150000
#define DD      64
#define NNZ_UI  2000000
#define NNZ_S   1000000
#define BB      4096
#define LRELU   0.01f
#define LN_EPS  1e-5f
#define BM_WORDS ((IIN + 31) / 32)

// ---------------- scratch (device globals; allocation-free rule) ----------------
__device__ __align__(128) float g_u1[UN * DD];   // user layer-1
__device__ __align__(128) float g_u2[UN * DD];   // user layer-2 (= social cur0)
__device__ __align__(128) float g_i1[IIN * DD];  // item layer-1
__device__ __align__(128) float g_i2[IIN * DD];  // item layer-2 (sparse: only pos rows valid)
__device__ __align__(128) float g_c1[UN * DD];   // social cur1
__device__ __align__(128) float g_c2[UN * DD];   // social cur2
__device__ __align__(128) float g_xw[UN * DD];   // cur @ Wsoc[l]
__device__ __align__(128) float g_nb[UN * DD];   // new = cur + neighbor (accumulated)
__device__ unsigned g_bm[BM_WORDS];              // pos_items membership bitmap

__device__ __forceinline__ void atomic_add_f4(float* p, float4 v) {
#if defined(__CUDA_ARCH__) && (__CUDA_ARCH__ >= 900)
    atomicAdd(reinterpret_cast<float4*>(p), v);
#else
    atomicAdd(p + 0, v.x); atomicAdd(p + 1, v.y);
    atomicAdd(p + 2, v.z); atomicAdd(p + 3, v.w);
#endif
}

// ---------------- init: u1=u2=0.1*E0u, i1=i2=0.1*E0i; zero bitmap ----------------
__global__ void k_init(const float4* __restrict__ Eu, const float4* __restrict__ Ei) {
    int idx = blockIdx.x * blockDim.x + threadIdx.x;
    const int NU = UN * DD / 4;
    const int NI = IIN * DD / 4;
    if (idx < BM_WORDS) g_bm[idx] = 0u;
    if (idx < NU) {
        float4 v = Eu[idx];
        v.x *= 0.1f; v.y *= 0.1f; v.z *= 0.1f; v.w *= 0.1f;
        reinterpret_cast<float4*>(g_u1)[idx] = v;
        reinterpret_cast<float4*>(g_u2)[idx] = v;
    } else if (idx < NU + NI) {
        int j = idx - NU;
        float4 v = Ei[j];
        v.x *= 0.1f; v.y *= 0.1f; v.z *= 0.1f; v.w *= 0.1f;
        reinterpret_cast<float4*>(g_i1)[j] = v;
        reinterpret_cast<float4*>(g_i2)[j] = v;
    }
}

__global__ void k_bm_set(const int* __restrict__ pos) {
    int i = blockIdx.x * blockDim.x + threadIdx.x;
    if (i < BB) {
        int p = __ldg(pos + i);
        atomicOr(&g_bm[p >> 5], 1u << (p & 31));
    }
}

// ---------------- dual-direction UI SpMM: one warp per edge ----------------
// lanes 0-15 : out_u[src] += w * x_i[dst]
// lanes 16-31: out_i[dst] += w * x_u[src]   (layer 1: only if dst in pos bitmap)
__global__ void k_spmm_ui(const int* __restrict__ src, const int* __restrict__ dst,
                          const float* __restrict__ w,
                          const float* __restrict__ E0u, const float* __restrict__ E0i,
                          int layer) {
    int t = blockIdx.x * blockDim.x + threadIdx.x;
    int e = t >> 5;
    if (e >= NNZ_UI) return;
    int lane = t & 31;
    int q = lane & 15;

    const float* xu = (layer == 0) ? E0u : g_u1;
    const float* xi = (layer == 0) ? E0i : g_i1;
    float* outu = (layer == 0) ? g_u1 : g_u2;
    float* outi = (layer == 0) ? g_i1 : g_i2;

    int   s  = __ldg(src + e);
    int   d  = __ldg(dst + e);
    float we = __ldg(w + e);

    if (lane < 16) {
        float4 v = __ldg(reinterpret_cast<const float4*>(xi + (size_t)d * DD) + q);
        v.x *= we; v.y *= we; v.z *= we; v.w *= we;
        atomic_add_f4(outu + (size_t)s * DD + q * 4, v);
    } else {
        if (layer == 1) {
            // i2 only consumed at pos_items rows — skip everything else
            if (!((g_bm[d >> 5] >> (d & 31)) & 1u)) return;
        }
        float4 v = __ldg(reinterpret_cast<const float4*>(xu + (size_t)s * DD) + q);
        v.x *= we; v.y *= we; v.z *= we; v.w *= we;
        atomic_add_f4(outi + (size_t)d * DD + q * 4, v);
    }
}

// ---------------- social SpMM: nb[s_src] += s_w * Xw[s_dst] (16 thr/edge) ----------------
__global__ void k_spmm_s(const int* __restrict__ r_idx, const int* __restrict__ c_idx,
                         const float* __restrict__ w) {
    int t = blockIdx.x * blockDim.x + threadIdx.x;
    int e = t >> 4;
    if (e >= NNZ_S) return;
    int q = t & 15;
    int   r  = __ldg(r_idx + e);
    int   c  = __ldg(c_idx + e);
    float we = __ldg(w + e);
    float4 v = __ldg(reinterpret_cast<const float4*>(g_xw + (size_t)c * DD) + q);
    v.x *= we; v.y *= we; v.z *= we; v.w *= we;
    atomic_add_f4(g_nb + (size_t)r * DD + q * 4, v);
}

// ---------------- Xw = u2 @ Wsoc[0]; seed nb = u2. Register-blocked, grid-stride ----------------
// 256 threads, 8 warps; each warp does 4 rows with row data in registers (shfl broadcast).
__global__ void k_xw(const float* __restrict__ W) {
    __shared__ float Ws[DD * DD];
    int t = threadIdx.x;
    for (int i = t; i < DD * DD; i += 256) Ws[i] = W[i];
    __syncthreads();

    int wrp = t >> 5, lane = t & 31;
    const int ROWS_PER_BLOCK = 32;                  // 8 warps x 4 rows
    for (int rb = blockIdx.x; rb * ROWS_PER_BLOCK < UN; rb += gridDim.x) {
        int row0 = rb * ROWS_PER_BLOCK + wrp * 4;
        float a0[4], a1[4];
#pragma unroll
        for (int r = 0; r < 4; r++) {
            int row = row0 + r;
            if (row < UN) {
                a0[r] = g_u2[(size_t)row * DD + lane];
                a1[r] = g_u2[(size_t)row * DD + lane + 32];
                g_nb[(size_t)row * DD + lane]      = a0[r];
                g_nb[(size_t)row * DD + lane + 32] = a1[r];
            } else { a0[r] = 0.f; a1[r] = 0.f; }
        }
        float acc0[4] = {0, 0, 0, 0}, acc1[4] = {0, 0, 0, 0};
#pragma unroll
        for (int k = 0; k < 32; k++) {
            float w0 = Ws[k * DD + lane], w1 = Ws[k * DD + lane + 32];
#pragma unroll
            for (int r = 0; r < 4; r++) {
                float a = __shfl_sync(0xffffffffu, a0[r], k);
                acc0[r] += a * w0; acc1[r] += a * w1;
            }
        }
#pragma unroll
        for (int k = 0; k < 32; k++) {
            float w0 = Ws[(k + 32) * DD + lane], w1 = Ws[(k + 32) * DD + lane + 32];
#pragma unroll
            for (int r = 0; r < 4; r++) {
                float a = __shfl_sync(0xffffffffu, a1[r], k);
                acc0[r] += a * w0; acc1[r] += a * w1;
            }
        }
#pragma unroll
        for (int r = 0; r < 4; r++) {
            int row = row0 + r;
            if (row < UN) {
                g_xw[(size_t)row * DD + lane]      = acc0[r];
                g_xw[(size_t)row * DD + lane + 32] = acc1[r];
            }
        }
    }
}

// ---------------- gated residual (+ fused next-layer Xw when layer==0) ----------------
// cur_next = gate*new + (1-gate)*cur, gate = sigmoid(lrelu(LN(new@ho_W + ho_b)))
// layer==0: additionally g_nb = cur_next, g_xw = cur_next @ Wsoc[1]
__global__ void k_gate(const float* __restrict__ hoW, const float* __restrict__ hob,
                       const float* __restrict__ hog, const float* __restrict__ hobeta,
                       const float* __restrict__ W2, int layer) {
    __shared__ float Ws[DD * DD];
    __shared__ float Ws2[DD * DD];
    int t = threadIdx.x;                           // 256 threads, 8 warps
    for (int i = t; i < DD * DD; i += 256) {
        Ws[i] = hoW[i];
        if (layer == 0) Ws2[i] = W2[i];
    }
    __syncthreads();

    const float* cur = (layer == 0) ? g_u2 : g_c1;
    float* outp      = (layer == 0) ? g_c1 : g_c2;

    int wrp = t >> 5, lane = t & 31;
    float hb0 = __ldg(hob + lane),    hb1 = __ldg(hob + lane + 32);
    float hg0 = __ldg(hog + lane),    hg1 = __ldg(hog + lane + 32);
    float hB0 = __ldg(hobeta + lane), hB1 = __ldg(hobeta + lane + 32);

    for (int rb = blockIdx.x; rb * 8 < UN; rb += gridDim.x) {
        int row = rb * 8 + wrp;
        if (row >= UN) continue;
        size_t base = (size_t)row * DD;
        float n0 = g_nb[base + lane], n1 = g_nb[base + lane + 32];

        float h0 = hb0, h1 = hb1;
#pragma unroll
        for (int k = 0; k < 32; k++) {
            float a = __shfl_sync(0xffffffffu, n0, k);
            h0 += a * Ws[k * DD + lane];
            h1 += a * Ws[k * DD + lane + 32];
        }
#pragma unroll
        for (int k = 0; k < 32; k++) {
            float a = __shfl_sync(0xffffffffu, n1, k);
            h0 += a * Ws[(k + 32) * DD + lane];
            h1 += a * Ws[(k + 32) * DD + lane + 32];
        }
        // layernorm over 64 (2 per lane)
        float s = h0 + h1;
#pragma unroll
        for (int o = 16; o; o >>= 1) s += __shfl_xor_sync(0xffffffffu, s, o);
        float mu = s * (1.0f / 64.0f);
        float d0 = h0 - mu, d1 = h1 - mu;
        float v = d0 * d0 + d1 * d1;
#pragma unroll
        for (int o = 16; o; o >>= 1) v += __shfl_xor_sync(0xffffffffu, v, o);
        float inv = rsqrtf(v * (1.0f / 64.0f) + LN_EPS);
        float y0 = d0 * inv * hg0 + hB0;
        float y1 = d1 * inv * hg1 + hB1;
        float p0 = (y0 >= 0.f) ? y0 : LRELU * y0;
        float p1 = (y1 >= 0.f) ? y1 : LRELU * y1;
        float gt0 = 1.f / (1.f + __expf(-p0));
        float gt1 = 1.f / (1.f + __expf(-p1));
        float c0 = cur[base + lane], c1 = cur[base + lane + 32];
        float o0 = gt0 * n0 + (1.f - gt0) * c0;
        float o1 = gt1 * n1 + (1.f - gt1) * c1;
        outp[base + lane]      = o0;
        outp[base + lane + 32] = o1;

        if (layer == 0) {
            // fused: seed nb for next social layer and compute its Xw
            g_nb[base + lane]      = o0;
            g_nb[base + lane + 32] = o1;
            float acc0 = 0.f, acc1 = 0.f;
#pragma unroll
            for (int k = 0; k < 32; k++) {
                float a = __shfl_sync(0xffffffffu, o0, k);
                acc0 += a * Ws2[k * DD + lane];
                acc1 += a * Ws2[k * DD + lane + 32];
            }
#pragma unroll
            for (int k = 0; k < 32; k++) {
                float a = __shfl_sync(0xffffffffu, o1, k);
                acc0 += a * Ws2[(k + 32) * DD + lane];
                acc1 += a * Ws2[(k + 32) * DD + lane + 32];
            }
            g_xw[base + lane]      = acc0;
            g_xw[base + lane + 32] = acc1;
        }
    }
}

// ---------------- scoring: deferred aggregation + fusion GEMM + LN + dot ----------------
__global__ void k_score(const int* __restrict__ users, const int* __restrict__ pos,
                        const float* __restrict__ E0u, const float* __restrict__ E0i,
                        const float* __restrict__ lw,
                        const float* __restrict__ mpW, const float* __restrict__ mpb,
                        const float* __restrict__ mpg, const float* __restrict__ mpbeta,
                        float* __restrict__ out) {
    __shared__ float Ws[2 * DD * DD];              // 128x64 = 32 KB
    __shared__ float rows[8][2 * DD];
    int t = threadIdx.x;                           // 256 threads, 8 warps
    for (int i = t; i < 2 * DD * DD; i += 256) Ws[i] = mpW[i];
    int wrp = t >> 5, lane = t & 31;
    int b = blockIdx.x * 8 + wrp;

    // softmax over layer_weights[:3]
    float l0 = __ldg(lw), l1 = __ldg(lw + 1), l2 = __ldg(lw + 2);
    float m = fmaxf(l0, fmaxf(l1, l2));
    float e0 = __expf(l0 - m), e1 = __expf(l1 - m), e2 = __expf(l2 - m);
    float wi = 1.f / (e0 + e1 + e2);
    float w0 = e0 * wi, w1 = e1 * wi, w2 = e2 * wi;

    float f0 = 0.f, f1 = 0.f, f2 = 0.f, f3 = 0.f;
    int p = 0;
    if (b < BB) {
        int u = __ldg(users + b);
        p = __ldg(pos + b);
        size_t ub = (size_t)u * DD;
        f0 = w0 * E0u[ub + lane]      + w1 * g_u1[ub + lane]      + w2 * g_u2[ub + lane];
        f1 = w0 * E0u[ub + lane + 32] + w1 * g_u1[ub + lane + 32] + w2 * g_u2[ub + lane + 32];
        f2 = w0 * g_u2[ub + lane]      + w1 * g_c1[ub + lane]      + w2 * g_c2[ub + lane];
        f3 = w0 * g_u2[ub + lane + 32] + w1 * g_c1[ub + lane + 32] + w2 * g_c2[ub + lane + 32];
    }
    rows[wrp][lane] = f0; rows[wrp][lane + 32] = f1;
    rows[wrp][64 + lane] = f2; rows[wrp][96 + lane] = f3;
    __syncthreads();
    if (b >= BB) return;

    float h0 = __ldg(mpb + lane), h1 = __ldg(mpb + lane + 32);
#pragma unroll
    for (int k = 0; k < 2 * DD; k++) {
        float a = rows[wrp][k];
        h0 += a * Ws[k * DD + lane];
        h1 += a * Ws[k * DD + lane + 32];
    }
    float s = h0 + h1;
#pragma unroll
    for (int o = 16; o; o >>= 1) s += __shfl_xor_sync(0xffffffffu, s, o);
    float mu = s * (1.0f / 64.0f);
    float d0 = h0 - mu, d1 = h1 - mu;
    float v = d0 * d0 + d1 * d1;
#pragma unroll
    for (int o = 16; o; o >>= 1) v += __shfl_xor_sync(0xffffffffu, v, o);
    float inv = rsqrtf(v * (1.0f / 64.0f) + LN_EPS);
    float y0 = d0 * inv * __ldg(mpg + lane)      + __ldg(mpbeta + lane);
    float y1 = d1 * inv * __ldg(mpg + lane + 32) + __ldg(mpbeta + lane + 32);
    float fo0 = (y0 >= 0.f) ? y0 : LRELU * y0;
    float fo1 = (y1 >= 0.f) ? y1 : LRELU * y1;

    size_t pb = (size_t)p * DD;
    float iw0 = w0 * E0i[pb + lane]      + w1 * g_i1[pb + lane]      + w2 * g_i2[pb + lane];
    float iw1 = w0 * E0i[pb + lane + 32] + w1 * g_i1[pb + lane + 32] + w2 * g_i2[pb + lane + 32];

    float part = fo0 * iw0 + fo1 * iw1;
#pragma unroll
    for (int o = 16; o; o >>= 1) part += __shfl_xor_sync(0xffffffffu, part, o);
    if (lane == 0) out[b] = part;
}

// ---------------- launch ----------------
extern "C" void kernel_launch(void* const* d_in, const int* in_sizes, int n_in,
                              void* d_out, int out_size) {
    const int*   users  = (const int*)d_in[0];
    const int*   pos    = (const int*)d_in[1];
    const int*   ui_src = (const int*)d_in[2];
    const int*   ui_dst = (const int*)d_in[3];
    const float* ui_w   = (const float*)d_in[4];
    const int*   s_src  = (const int*)d_in[5];
    const int*   s_dst  = (const int*)d_in[6];
    const float* s_w    = (const float*)d_in[7];
    const float* Eu     = (const float*)d_in[8];
    const float* Ei     = (const float*)d_in[9];
    const float* lw     = (const float*)d_in[10];
    const float* Wsoc   = (const float*)d_in[11];
    const float* hoW    = (const float*)d_in[12];
    const float* hob    = (const float*)d_in[13];
    const float* hog    = (const float*)d_in[14];
    const float* hobeta = (const float*)d_in[15];
    const float* mpW    = (const float*)d_in[16];
    const float* mpb    = (const float*)d_in[17];
    const float* mpg    = (const float*)d_in[18];
    const float* mpbeta = (const float*)d_in[19];
    float* out = (float*)d_out;

    // LightGCN
    k_init<<<(UN * DD / 4 + IIN * DD / 4 + 255) / 256, 256>>>(
        (const float4*)Eu, (const float4*)Ei);
    k_bm_set<<<(BB + 255) / 256, 256>>>(pos);
    k_spmm_ui<<<(NNZ_UI * 32 + 255) / 256, 256>>>(ui_src, ui_dst, ui_w, Eu, Ei, 0);
    k_spmm_ui<<<(NNZ_UI * 32 + 255) / 256, 256>>>(ui_src, ui_dst, ui_w, Eu, Ei, 1);

    // Social layer 0: Xw (+ nb seed) -> SpMM -> gate (+ fused layer-1 Xw/nb)
    k_xw<<<1024, 256>>>(Wsoc);
    k_spmm_s<<<(NNZ_S * 16 + 255) / 256, 256>>>(s_src, s_dst, s_w);
    k_gate<<<1024, 256>>>(hoW, hob, hog, hobeta, Wsoc + DD * DD, 0);

    // Social layer 1: SpMM -> gate
    k_spmm_s<<<(NNZ_S * 16 + 255) / 256, 256>>>(s_src, s_dst, s_w);
    k_gate<<<1024, 256>>>(hoW, hob, hog, hobeta, (const float*)nullptr, 1);

    // Deferred aggregation + metapath fusion + scoring
    k_score<<<(BB + 7) / 8, 256>>>(users, pos, Eu, Ei, lw,
                                   mpW, mpb, mpg, mpbeta, out);
}